// round 14
// baseline (speedup 1.0000x reference)
#include <cuda_runtime.h>
#include <cstdint>
#include <cstddef>

#define BB 8
#define TT 2048
#define CC 1024
#define HH 128

// Scratch (device globals — no runtime alloc).
__device__ float g_q[BB * TT * HH];   // d-interleaved layout
__device__ float g_k[BB * TT * HH];   // d-interleaved layout
__device__ float g_v[BB * TT * HH];   // natural layout
// Split-KV partials: [part][(qt-16)*8+b][64*128] unnormalized O; m,l per row.
__device__ float g_po[2][128][64 * 128];
__device__ float g_pm[2][128][64];
__device__ float g_pl[2][128][64];

// Attention job table, LPT order (descending KV-tile count).
// part: 0 = KV[0,h), 1 = KV[h,qt+1), 2 = full; h = (qt+1)>>1.
__constant__ signed char c_qt[48] = {
    31,31,30,15,30,29,29,28,14,28,27,27,26,13,26,25,25,24,12,24,
    23,23,22,11,22,21,21,20,10,20,19,19,18, 9,18,17,17,16, 8,16,
     7, 6, 5, 4, 3, 2, 1, 0 };
__constant__ signed char c_part[48] = {
     0, 1, 1, 2, 0, 0, 1, 1, 2, 0, 0, 1, 1, 2, 0, 0, 1, 1, 2, 0,
     0, 1, 1, 2, 0, 0, 1, 1, 2, 0, 0, 1, 1, 2, 0, 0, 1, 1, 2, 0,
     2, 2, 2, 2, 2, 2, 2, 2 };

// ---------------------------------------------------------------------------
// Helpers
// ---------------------------------------------------------------------------
__device__ __forceinline__ float tf32r(float x) {
    uint32_t u;
    asm("cvt.rna.tf32.f32 %0, %1;" : "=r"(u) : "f"(x));
    return __uint_as_float(u);
}
__device__ __forceinline__ uint32_t tf32u(float x) {
    uint32_t u;
    asm("cvt.rna.tf32.f32 %0, %1;" : "=r"(u) : "f"(x));
    return u;
}
__device__ __forceinline__ void cp16(uint32_t saddr, const float* gaddr) {
    asm volatile("cp.async.cg.shared.global [%0], [%1], 16;"
                 :: "r"(saddr), "l"(gaddr));
}
__device__ __forceinline__ void cp_commit() {
    asm volatile("cp.async.commit_group;");
}
__device__ __forceinline__ float fex2(float x) {
    float r;
    asm("ex2.approx.f32 %0, %1;" : "=f"(r) : "f"(x));
    return r;
}
__device__ __forceinline__ void mma8(float* c, const uint32_t* a,
                                     uint32_t b0, uint32_t b1) {
    asm volatile(
        "mma.sync.aligned.m16n8k8.row.col.f32.tf32.tf32.f32 "
        "{%0,%1,%2,%3}, {%4,%5,%6,%7}, {%8,%9}, {%0,%1,%2,%3};"
        : "+f"(c[0]), "+f"(c[1]), "+f"(c[2]), "+f"(c[3])
        : "r"(a[0]), "r"(a[1]), "r"(a[2]), "r"(a[3]), "r"(b0), "r"(b1));
}

// ---------------------------------------------------------------------------
// QKV projection GEMM, tf32 mma.sync, 3-stage cp.async pipeline (R12 config).
// CTA 128x128, BK=32, 128 thr = 4 warps of 64x64. Grid (3, 64) per half:
// mblk = mbase + blockIdx.y. 192 CTAs/half -> single wave at 2 CTAs/SM.
// Epilogue writes q/k d-interleaved (per 8-group: [0,4,1,5,2,6,3,7]).
// ---------------------------------------------------------------------------
#define AST 36
#define BST 136
#define A_FL (128 * AST)
#define B_FL (32 * BST)
#define STG_FL (A_FL + B_FL)

__global__ __launch_bounds__(128, 2) void qkv_mma_kernel(
    const float* __restrict__ X,
    const float* __restrict__ Wq,
    const float* __restrict__ Wk,
    const float* __restrict__ Wv,
    int mbase)
{
    extern __shared__ float smem[];

    const int proj = blockIdx.x;
    const int mblk = mbase + blockIdx.y;
    const float* __restrict__ W = (proj == 0) ? Wq : (proj == 1) ? Wk : Wv;
    float* __restrict__ out     = (proj == 0) ? g_q : (proj == 1) ? g_k : g_v;

    const int tid  = threadIdx.x;
    const int wid  = tid >> 5;
    const int lane = tid & 31;
    const int g    = lane >> 2;
    const int tg   = lane & 3;
    const int wm   = wid & 1;
    const int wn   = wid >> 1;

    const uint32_t smema = (uint32_t)__cvta_generic_to_shared(smem);
    const float* Xb = X + (size_t)mblk * 128 * CC;

    auto issue_chunk = [&](int kc) {
        const uint32_t sAa = smema + (uint32_t)((kc % 3) * STG_FL) * 4;
        const uint32_t sBa = sAa + A_FL * 4;
#pragma unroll
        for (int it = 0; it < 8; it++) {
            int f  = tid + it * 128;
            int r  = f >> 3;
            int c4 = f & 7;
            cp16(sAa + (r * AST + c4 * 4) * 4, Xb + (size_t)r * CC + kc * 32 + c4 * 4);
        }
#pragma unroll
        for (int it = 0; it < 8; it++) {
            int f  = tid + it * 128;
            int r  = f >> 5;
            int c4 = f & 31;
            cp16(sBa + (r * BST + c4 * 4) * 4, W + (size_t)(kc * 32 + r) * HH + c4 * 4);
        }
        cp_commit();
    };

    float acc[4][8][4];
#pragma unroll
    for (int i = 0; i < 4; i++)
#pragma unroll
        for (int n = 0; n < 8; n++)
#pragma unroll
            for (int v = 0; v < 4; v++) acc[i][n][v] = 0.0f;

    issue_chunk(0);
    issue_chunk(1);

    for (int kc = 0; kc < 32; kc++) {
        if (kc < 31) asm volatile("cp.async.wait_group 1;");
        else         asm volatile("cp.async.wait_group 0;");
        __syncthreads();
        if (kc + 2 < 32) issue_chunk(kc + 2);

        const float* aB = smem + (kc % 3) * STG_FL;
        const float* bB = aB + A_FL;

#pragma unroll
        for (int ks = 0; ks < 4; ks++) {
            uint32_t af[4][4];
#pragma unroll
            for (int i = 0; i < 4; i++) {
                const int base = (wm * 64 + i * 16 + g) * AST + ks * 8 + tg;
                af[i][0] = tf32u(aB[base]);
                af[i][1] = tf32u(aB[base + 8 * AST]);
                af[i][2] = tf32u(aB[base + 4]);
                af[i][3] = tf32u(aB[base + 8 * AST + 4]);
            }
#pragma unroll
            for (int n = 0; n < 8; n++) {
                const int base = (ks * 8 + tg) * BST + wn * 64 + n * 8 + g;
                uint32_t b0 = tf32u(bB[base]);
                uint32_t b1 = tf32u(bB[base + 4 * BST]);
#pragma unroll
                for (int i = 0; i < 4; i++)
                    mma8(acc[i][n], af[i], b0, b1);
            }
        }
    }

    const int np = (tg < 2) ? (4 * tg) : (4 * tg - 7);
#pragma unroll
    for (int i = 0; i < 4; i++) {
        const int r0 = mblk * 128 + wm * 64 + i * 16 + g;
#pragma unroll
        for (int n = 0; n < 8; n++) {
            const int gbase = wn * 64 + n * 8;
            float v0 = tf32r(acc[i][n][0]);
            float v1 = tf32r(acc[i][n][1]);
            float v2 = tf32r(acc[i][n][2]);
            float v3 = tf32r(acc[i][n][3]);
            float* d0 = out + (size_t)r0 * HH;
            float* d1 = d0 + 8 * HH;
            if (proj < 2) {
                d0[gbase + np]     = v0;
                d0[gbase + np + 2] = v1;
                d1[gbase + np]     = v2;
                d1[gbase + np + 2] = v3;
            } else {
                *(float2*)(d0 + gbase + 2 * tg) = make_float2(v0, v1);
                *(float2*)(d1 + gbase + 2 * tg) = make_float2(v2, v3);
            }
        }
    }
}

// ---------------------------------------------------------------------------
// Causal flash attention, split-KV, tf32 mma.sync, 2 CTAs/SM, LPT schedule.
// Grid 192 per half: slot = bid>>2, b = bbase + (bid&3).
// ---------------------------------------------------------------------------
#define KST 136
#define VST 136

__global__ __launch_bounds__(128, 2) void attn_mma_kernel(float* __restrict__ Out,
                                                          int bbase)
{
    extern __shared__ float smem_f[];
    float* sQ = smem_f;
    float* sK = sQ + 64 * KST;
    float* sV = sK + 64 * KST;

    const int slot = blockIdx.x >> 2;
    const int b    = bbase + (blockIdx.x & 3);
    const int qt   = c_qt[slot];
    const int part = c_part[slot];
    const int h    = (qt + 1) >> 1;
    const int j0   = (part == 1) ? h : 0;
    const int j1   = (part == 0) ? h : (qt + 1);

    const int tid  = threadIdx.x;
    const int wid  = tid >> 5;
    const int lane = tid & 31;
    const int g    = lane >> 2;
    const int tg   = lane & 3;

    const uint32_t sQa = (uint32_t)__cvta_generic_to_shared(sQ);
    const uint32_t sKa = (uint32_t)__cvta_generic_to_shared(sK);
    const uint32_t sVa = (uint32_t)__cvta_generic_to_shared(sV);

    const float* Qb = g_q + ((size_t)b * TT + (size_t)qt * 64) * HH;
    const float* Kb = g_k + ((size_t)b * TT + (size_t)j0 * 64) * HH;
    const float* Vb = g_v + ((size_t)b * TT + (size_t)j0 * 64) * HH;

#pragma unroll
    for (int it = 0; it < 16; it++) {
        int f  = tid + it * 128;
        int r  = f >> 5;
        int c4 = f & 31;
        cp16(sQa + (r * KST + c4 * 4) * 4, Qb + r * HH + c4 * 4);
        cp16(sKa + (r * KST + c4 * 4) * 4, Kb + r * HH + c4 * 4);
    }
    cp_commit();
#pragma unroll
    for (int it = 0; it < 16; it++) {
        int f  = tid + it * 128;
        int r  = f >> 5;
        int c4 = f & 31;
        cp16(sVa + (r * VST + c4 * 4) * 4, Vb + r * HH + c4 * 4);
    }
    cp_commit();

    asm volatile("cp.async.wait_group 1;");
    __syncthreads();

    uint32_t qa[16][4];
#pragma unroll
    for (int ks = 0; ks < 16; ks++) {
        const float* qrow = sQ + (16 * wid + g) * KST + ks * 8 + 2 * tg;
        float2 f0 = *(const float2*)qrow;
        float2 f1 = *(const float2*)(qrow + 8 * KST);
        qa[ks][0] = __float_as_uint(f0.x);
        qa[ks][1] = __float_as_uint(f1.x);
        qa[ks][2] = __float_as_uint(f0.y);
        qa[ks][3] = __float_as_uint(f1.y);
    }

    float o[16][4];
#pragma unroll
    for (int n = 0; n < 16; n++)
#pragma unroll
        for (int v = 0; v < 4; v++) o[n][v] = 0.0f;
    float m0 = -1e30f, m1 = -1e30f, l0 = 0.0f, l1 = 0.0f;

    const float SCL = 0.08838834764831845f * 1.4426950408889634f;
    const int src0 = (lane & ~3) | (tg >> 1);
    const int src1 = src0 + 2;
    const bool odd = (tg & 1);

    for (int j = j0; j < j1; j++) {
        if (j > j0) {
            asm volatile("cp.async.wait_group 1;");
            __syncthreads();
        }

        float c[8][4];
#pragma unroll
        for (int n = 0; n < 8; n++)
#pragma unroll
            for (int v = 0; v < 4; v++) c[n][v] = 0.0f;

#pragma unroll
        for (int ks = 0; ks < 16; ks++) {
#pragma unroll
            for (int n = 0; n < 8; n++) {
                float2 kf = *(const float2*)&sK[(n * 8 + g) * KST + ks * 8 + 2 * tg];
                mma8(c[n], qa[ks], __float_as_uint(kf.x), __float_as_uint(kf.y));
            }
        }

        __syncthreads();
        if (j + 1 < j1) {
            const float* Kn = g_k + ((size_t)b * TT + (size_t)(j + 1) * 64) * HH;
#pragma unroll
            for (int it = 0; it < 16; it++) {
                int f  = tid + it * 128;
                int r  = f >> 5;
                int c4 = f & 31;
                cp16(sKa + (r * KST + c4 * 4) * 4, Kn + r * HH + c4 * 4);
            }
            cp_commit();
        }

#pragma unroll
        for (int n = 0; n < 8; n++)
#pragma unroll
            for (int v = 0; v < 4; v++) c[n][v] *= SCL;

        if (j == qt) {
            const int r0 = 16 * wid + g;
            const int r1 = r0 + 8;
#pragma unroll
            for (int n = 0; n < 8; n++) {
                const int col = 8 * n + 2 * tg;
                if (col     > r0) c[n][0] = -1e30f;
                if (col + 1 > r0) c[n][1] = -1e30f;
                if (col     > r1) c[n][2] = -1e30f;
                if (col + 1 > r1) c[n][3] = -1e30f;
            }
        }

        float rm0 = -1e30f, rm1 = -1e30f;
#pragma unroll
        for (int n = 0; n < 8; n++) {
            rm0 = fmaxf(rm0, fmaxf(c[n][0], c[n][1]));
            rm1 = fmaxf(rm1, fmaxf(c[n][2], c[n][3]));
        }
        rm0 = fmaxf(rm0, __shfl_xor_sync(0xffffffffu, rm0, 1));
        rm0 = fmaxf(rm0, __shfl_xor_sync(0xffffffffu, rm0, 2));
        rm1 = fmaxf(rm1, __shfl_xor_sync(0xffffffffu, rm1, 1));
        rm1 = fmaxf(rm1, __shfl_xor_sync(0xffffffffu, rm1, 2));

        const float m0n = fmaxf(m0, rm0);
        const float m1n = fmaxf(m1, rm1);
        const float a0  = fex2(m0 - m0n);
        const float a1  = fex2(m1 - m1n);

        float rs0 = 0.0f, rs1 = 0.0f;
#pragma unroll
        for (int n = 0; n < 8; n++) {
            c[n][0] = fex2(c[n][0] - m0n);
            c[n][1] = fex2(c[n][1] - m0n);
            c[n][2] = fex2(c[n][2] - m1n);
            c[n][3] = fex2(c[n][3] - m1n);
            rs0 += c[n][0] + c[n][1];
            rs1 += c[n][2] + c[n][3];
        }
        rs0 += __shfl_xor_sync(0xffffffffu, rs0, 1);
        rs0 += __shfl_xor_sync(0xffffffffu, rs0, 2);
        rs1 += __shfl_xor_sync(0xffffffffu, rs1, 1);
        rs1 += __shfl_xor_sync(0xffffffffu, rs1, 2);

        l0 = l0 * a0 + rs0;
        l1 = l1 * a1 + rs1;
        m0 = m0n;
        m1 = m1n;

#pragma unroll
        for (int n = 0; n < 16; n++) {
            o[n][0] *= a0; o[n][1] *= a0;
            o[n][2] *= a1; o[n][3] *= a1;
        }

#pragma unroll
        for (int n = 0; n < 8; n++)
#pragma unroll
            for (int v = 0; v < 4; v++) c[n][v] = tf32r(c[n][v]);

        if (j + 1 < j1) asm volatile("cp.async.wait_group 1;");
        else            asm volatile("cp.async.wait_group 0;");
        __syncthreads();

#pragma unroll
        for (int kk = 0; kk < 8; kk++) {
            float v00 = __shfl_sync(0xffffffffu, c[kk][0], src0);
            float v01 = __shfl_sync(0xffffffffu, c[kk][1], src0);
            float v10 = __shfl_sync(0xffffffffu, c[kk][2], src0);
            float v11 = __shfl_sync(0xffffffffu, c[kk][3], src0);
            float v20 = __shfl_sync(0xffffffffu, c[kk][0], src1);
            float v21 = __shfl_sync(0xffffffffu, c[kk][1], src1);
            float v30 = __shfl_sync(0xffffffffu, c[kk][2], src1);
            float v31 = __shfl_sync(0xffffffffu, c[kk][3], src1);
            uint32_t pa[4];
            pa[0] = __float_as_uint(odd ? v01 : v00);
            pa[1] = __float_as_uint(odd ? v11 : v10);
            pa[2] = __float_as_uint(odd ? v21 : v20);
            pa[3] = __float_as_uint(odd ? v31 : v30);
#pragma unroll
            for (int n = 0; n < 16; n++) {
                const int base = (kk * 8 + tg) * VST + 8 * n + g;
                uint32_t b0 = __float_as_uint(sV[base]);
                uint32_t b1 = __float_as_uint(sV[base + 4 * VST]);
                mma8(o[n], pa, b0, b1);
            }
        }

        __syncthreads();
        if (j + 1 < j1) {
            const float* Vn = g_v + ((size_t)b * TT + (size_t)(j + 1) * 64) * HH;
#pragma unroll
            for (int it = 0; it < 16; it++) {
                int f  = tid + it * 128;
                int r  = f >> 5;
                int c4 = f & 31;
                cp16(sVa + (r * VST + c4 * 4) * 4, Vn + r * HH + c4 * 4);
            }
            cp_commit();
        }
    }

    // ----- epilogue -----
    const int r0 = 16 * wid + g;
    if (part == 2) {
        const float inv0 = 1.0f / l0;
        const float inv1 = 1.0f / l1;
        float* p0 = Out + ((size_t)b * TT + qt * 64 + r0) * HH;
        float* p1 = p0 + 8 * HH;
#pragma unroll
        for (int n = 0; n < 16; n++) {
            const int col = 8 * n + 2 * tg;
            *(float2*)(p0 + col) = make_float2(o[n][0] * inv0, o[n][1] * inv0);
            *(float2*)(p1 + col) = make_float2(o[n][2] * inv1, o[n][3] * inv1);
        }
    } else {
        const int pidx = (qt - 16) * 8 + b;
        float* p0 = g_po[part][pidx] + r0 * 128;
        float* p1 = p0 + 8 * 128;
#pragma unroll
        for (int n = 0; n < 16; n++) {
            const int col = 8 * n + 2 * tg;
            *(float2*)(p0 + col) = make_float2(o[n][0], o[n][1]);
            *(float2*)(p1 + col) = make_float2(o[n][2], o[n][3]);
        }
        if (tg == 0) {
            g_pm[part][pidx][r0]     = m0;
            g_pm[part][pidx][r0 + 8] = m1;
            g_pl[part][pidx][r0]     = l0;
            g_pl[part][pidx][r0 + 8] = l1;
        }
    }
}

// ---------------------------------------------------------------------------
// Combine split-KV partials for 4 batches. Grid 256 per half.
// ---------------------------------------------------------------------------
__global__ __launch_bounds__(256) void combine_kernel(float* __restrict__ Out,
                                                      int bbase)
{
    const int idx4 = blockIdx.x >> 2;       // 0..63 : (qt-16)*4 + bloc
    const int quar = blockIdx.x & 3;
    const int qt   = 16 + (idx4 >> 2);
    const int b    = bbase + (idx4 & 3);
    const int pidx = (qt - 16) * 8 + b;
    const int tid  = threadIdx.x;

    const float* O0 = g_po[0][pidx];
    const float* O1 = g_po[1][pidx];
    const float* M0 = g_pm[0][pidx];
    const float* M1 = g_pm[1][pidx];
    const float* L0 = g_pl[0][pidx];
    const float* L1 = g_pl[1][pidx];
    float* dst = Out + ((size_t)b * TT + (size_t)qt * 64) * HH;

#pragma unroll
    for (int it = 0; it < 2; it++) {
        int f  = tid + it * 256;
        int r  = quar * 16 + (f >> 5);
        int c4 = f & 31;
        float m0v = M0[r], m1v = M1[r];
        float mv  = fmaxf(m0v, m1v);
        float w0  = fex2(m0v - mv);
        float w1  = fex2(m1v - mv);
        float inv = 1.0f / (L0[r] * w0 + L1[r] * w1);
        float4 a  = *(const float4*)(O0 + r * 128 + c4 * 4);
        float4 bb = *(const float4*)(O1 + r * 128 + c4 * 4);
        float4 res = make_float4((a.x * w0 + bb.x * w1) * inv,
                                 (a.y * w0 + bb.y * w1) * inv,
                                 (a.z * w0 + bb.z * w1) * inv,
                                 (a.w * w0 + bb.w * w1) * inv);
        *(float4*)(dst + r * 128 + c4 * 4) = res;
    }
}

// ---------------------------------------------------------------------------
extern "C" void kernel_launch(void* const* d_in, const int* in_sizes, int n_in,
                              void* d_out, int out_size)
{
    const float* x  = (const float*)d_in[0];
    const float* Wq = (const float*)d_in[1];
    const float* Wk = (const float*)d_in[2];
    const float* Wv = (const float*)d_in[3];
    float* out = (float*)d_out;

    (void)in_sizes; (void)n_in; (void)out_size;

    // One-time host-side resources (identical captured work every call).
    static cudaStream_t s2 = nullptr;
    static cudaEvent_t evA = nullptr, evJ = nullptr;
    if (s2 == nullptr) {
        cudaStreamCreateWithFlags(&s2, cudaStreamNonBlocking);
        cudaEventCreateWithFlags(&evA, cudaEventDisableTiming);
        cudaEventCreateWithFlags(&evJ, cudaEventDisableTiming);
    }

    const int gemm_smem = 3 * STG_FL * (int)sizeof(float);
    cudaFuncSetAttribute(qkv_mma_kernel,
                         cudaFuncAttributeMaxDynamicSharedMemorySize, gemm_smem);
    const int attn_smem = 64 * (2 * KST + VST) * (int)sizeof(float);
    cudaFuncSetAttribute(attn_mma_kernel,
                         cudaFuncAttributeMaxDynamicSharedMemorySize, attn_smem);

    // GEMM half A (batches 0-3), then fork.
    qkv_mma_kernel<<<dim3(3, 64), 128, gemm_smem>>>(x, Wq, Wk, Wv, 0);
    cudaEventRecord(evA, 0);

    // Main stream: GEMM half B (batches 4-7) -> attention B -> combine B.
    qkv_mma_kernel<<<dim3(3, 64), 128, gemm_smem>>>(x, Wq, Wk, Wv, 64);

    // Forked stream: attention A + combine A, concurrent with GEMM B.
    cudaStreamWaitEvent(s2, evA, 0);
    attn_mma_kernel<<<192, 128, attn_smem, s2>>>(out, 0);
    combine_kernel<<<256, 256, 0, s2>>>(out, 0);
    cudaEventRecord(evJ, s2);

    attn_mma_kernel<<<192, 128, attn_smem>>>(out, 4);
    combine_kernel<<<256, 256>>>(out, 4);

    // Join fork back into the main stream.
    cudaStreamWaitEvent(0, evJ, 0);
}

// round 15
// speedup vs baseline: 1.1772x; 1.1772x over previous
#include <cuda_runtime.h>
#include <cstdint>
#include <cstddef>

#define BB 8
#define TT 2048
#define CC 1024
#define HH 128

// Scratch (device globals — no runtime alloc).
__device__ float g_q[BB * TT * HH];   // d-interleaved layout
__device__ float g_k[BB * TT * HH];   // d-interleaved layout
__device__ float g_v[BB * TT * HH];   // natural layout
// Split-KV partials: [part 0..2][(qt-10)*8+b][64*128] unnormalized O; m,l rows.
__device__ float g_po[3][176][64 * 128];
__device__ float g_pm[3][176][64];
__device__ float g_pl[3][176][64];

// Attention job table, strict LPT order (descending KV-tile count).
// part: 0/1/2 = split piece; 3 = full tile (qt < 10).
// Split rule: np = (qt>=24)?3:2, n = qt+1, piece p covers [p*n/np, (p+1)*n/np).
__constant__ signed char c_qt[62] = {
    23,23,22, 22,21,21,20,30,31,31,
    20,19,19,18, 9,27,28,28,29,29,29,30,30,31,
    18,17,17,16, 8,24,25,25,26,26,26,27,27,28,
    16,15,15,14, 7,24,24,25,
    14,13,13,12, 6,
    12,11,11,10, 5,
    10, 4, 3, 2, 1, 0 };
__constant__ signed char c_part[62] = {
     0, 1, 1,  0, 0, 1, 1, 2, 1, 2,
     0, 0, 1, 1, 3, 2, 1, 2, 0, 1, 2, 0, 1, 0,
     0, 0, 1, 1, 3, 2, 1, 2, 0, 1, 2, 0, 1, 0,
     0, 0, 1, 1, 3, 0, 1, 0,
     0, 0, 1, 1, 3,
     0, 0, 1, 1, 3,
     0, 3, 3, 3, 3, 3 };

// ---------------------------------------------------------------------------
// Helpers
// ---------------------------------------------------------------------------
__device__ __forceinline__ float tf32r(float x) {
    uint32_t u;
    asm("cvt.rna.tf32.f32 %0, %1;" : "=r"(u) : "f"(x));
    return __uint_as_float(u);
}
__device__ __forceinline__ uint32_t tf32u(float x) {
    uint32_t u;
    asm("cvt.rna.tf32.f32 %0, %1;" : "=r"(u) : "f"(x));
    return u;
}
__device__ __forceinline__ void cp16(uint32_t saddr, const float* gaddr) {
    asm volatile("cp.async.cg.shared.global [%0], [%1], 16;"
                 :: "r"(saddr), "l"(gaddr));
}
__device__ __forceinline__ void cp_commit() {
    asm volatile("cp.async.commit_group;");
}
__device__ __forceinline__ float fex2(float x) {
    float r;
    asm("ex2.approx.f32 %0, %1;" : "=f"(r) : "f"(x));
    return r;
}
__device__ __forceinline__ void mma8(float* c, const uint32_t* a,
                                     uint32_t b0, uint32_t b1) {
    asm volatile(
        "mma.sync.aligned.m16n8k8.row.col.f32.tf32.tf32.f32 "
        "{%0,%1,%2,%3}, {%4,%5,%6,%7}, {%8,%9}, {%0,%1,%2,%3};"
        : "+f"(c[0]), "+f"(c[1]), "+f"(c[2]), "+f"(c[3])
        : "r"(a[0]), "r"(a[1]), "r"(a[2]), "r"(a[3]), "r"(b0), "r"(b1));
}

// ---------------------------------------------------------------------------
// QKV projection GEMM, tf32 mma.sync, 3-stage cp.async pipeline (R12 exact).
// CTA 128x128, BK=32, 128 thr = 4 warps of 64x64. Grid (3, 128).
// Epilogue writes q/k d-interleaved (per 8-group: [0,4,1,5,2,6,3,7]).
// ---------------------------------------------------------------------------
#define AST 36
#define BST 136
#define A_FL (128 * AST)
#define B_FL (32 * BST)
#define STG_FL (A_FL + B_FL)

__global__ __launch_bounds__(128, 2) void qkv_mma_kernel(
    const float* __restrict__ X,
    const float* __restrict__ Wq,
    const float* __restrict__ Wk,
    const float* __restrict__ Wv)
{
    extern __shared__ float smem[];

    const int proj = blockIdx.x;
    const int mblk = blockIdx.y;
    const float* __restrict__ W = (proj == 0) ? Wq : (proj == 1) ? Wk : Wv;
    float* __restrict__ out     = (proj == 0) ? g_q : (proj == 1) ? g_k : g_v;

    const int tid  = threadIdx.x;
    const int wid  = tid >> 5;
    const int lane = tid & 31;
    const int g    = lane >> 2;
    const int tg   = lane & 3;
    const int wm   = wid & 1;
    const int wn   = wid >> 1;

    const uint32_t smema = (uint32_t)__cvta_generic_to_shared(smem);
    const float* Xb = X + (size_t)mblk * 128 * CC;

    auto issue_chunk = [&](int kc) {
        const uint32_t sAa = smema + (uint32_t)((kc % 3) * STG_FL) * 4;
        const uint32_t sBa = sAa + A_FL * 4;
#pragma unroll
        for (int it = 0; it < 8; it++) {
            int f  = tid + it * 128;
            int r  = f >> 3;
            int c4 = f & 7;
            cp16(sAa + (r * AST + c4 * 4) * 4, Xb + (size_t)r * CC + kc * 32 + c4 * 4);
        }
#pragma unroll
        for (int it = 0; it < 8; it++) {
            int f  = tid + it * 128;
            int r  = f >> 5;
            int c4 = f & 31;
            cp16(sBa + (r * BST + c4 * 4) * 4, W + (size_t)(kc * 32 + r) * HH + c4 * 4);
        }
        cp_commit();
    };

    float acc[4][8][4];
#pragma unroll
    for (int i = 0; i < 4; i++)
#pragma unroll
        for (int n = 0; n < 8; n++)
#pragma unroll
            for (int v = 0; v < 4; v++) acc[i][n][v] = 0.0f;

    issue_chunk(0);
    issue_chunk(1);

    for (int kc = 0; kc < 32; kc++) {
        if (kc < 31) asm volatile("cp.async.wait_group 1;");
        else         asm volatile("cp.async.wait_group 0;");
        __syncthreads();
        if (kc + 2 < 32) issue_chunk(kc + 2);

        const float* aB = smem + (kc % 3) * STG_FL;
        const float* bB = aB + A_FL;

#pragma unroll
        for (int ks = 0; ks < 4; ks++) {
            uint32_t af[4][4];
#pragma unroll
            for (int i = 0; i < 4; i++) {
                const int base = (wm * 64 + i * 16 + g) * AST + ks * 8 + tg;
                af[i][0] = tf32u(aB[base]);
                af[i][1] = tf32u(aB[base + 8 * AST]);
                af[i][2] = tf32u(aB[base + 4]);
                af[i][3] = tf32u(aB[base + 8 * AST + 4]);
            }
#pragma unroll
            for (int n = 0; n < 8; n++) {
                const int base = (ks * 8 + tg) * BST + wn * 64 + n * 8 + g;
                uint32_t b0 = tf32u(bB[base]);
                uint32_t b1 = tf32u(bB[base + 4 * BST]);
#pragma unroll
                for (int i = 0; i < 4; i++)
                    mma8(acc[i][n], af[i], b0, b1);
            }
        }
    }

    const int np = (tg < 2) ? (4 * tg) : (4 * tg - 7);
#pragma unroll
    for (int i = 0; i < 4; i++) {
        const int r0 = mblk * 128 + wm * 64 + i * 16 + g;
#pragma unroll
        for (int n = 0; n < 8; n++) {
            const int gbase = wn * 64 + n * 8;
            float v0 = tf32r(acc[i][n][0]);
            float v1 = tf32r(acc[i][n][1]);
            float v2 = tf32r(acc[i][n][2]);
            float v3 = tf32r(acc[i][n][3]);
            float* d0 = out + (size_t)r0 * HH;
            float* d1 = d0 + 8 * HH;
            if (proj < 2) {
                d0[gbase + np]     = v0;
                d0[gbase + np + 2] = v1;
                d1[gbase + np]     = v2;
                d1[gbase + np + 2] = v3;
            } else {
                *(float2*)(d0 + gbase + 2 * tg) = make_float2(v0, v1);
                *(float2*)(d1 + gbase + 2 * tg) = make_float2(v2, v3);
            }
        }
    }
}

// ---------------------------------------------------------------------------
// Causal flash attention, fine split-KV (up to 3-way), tf32 mma.sync,
// 2 CTAs/SM, LPT schedule. Grid 496: slot = bid>>3, b = bid&7.
// ---------------------------------------------------------------------------
#define KST 136
#define VST 136

__global__ __launch_bounds__(128, 2) void attn_mma_kernel(float* __restrict__ Out)
{
    extern __shared__ float smem_f[];
    float* sQ = smem_f;
    float* sK = sQ + 64 * KST;
    float* sV = sK + 64 * KST;

    const int slot = blockIdx.x >> 3;
    const int b    = blockIdx.x & 7;
    const int qt   = c_qt[slot];
    const int part = c_part[slot];
    const int n    = qt + 1;
    const int npt  = (qt >= 24) ? 3 : 2;
    int j0, j1;
    if (part == 3) { j0 = 0; j1 = n; }
    else           { j0 = (part * n) / npt; j1 = ((part + 1) * n) / npt; }

    const int tid  = threadIdx.x;
    const int wid  = tid >> 5;
    const int lane = tid & 31;
    const int g    = lane >> 2;
    const int tg   = lane & 3;

    const uint32_t sQa = (uint32_t)__cvta_generic_to_shared(sQ);
    const uint32_t sKa = (uint32_t)__cvta_generic_to_shared(sK);
    const uint32_t sVa = (uint32_t)__cvta_generic_to_shared(sV);

    const float* Qb = g_q + ((size_t)b * TT + (size_t)qt * 64) * HH;
    const float* Kb = g_k + ((size_t)b * TT + (size_t)j0 * 64) * HH;
    const float* Vb = g_v + ((size_t)b * TT + (size_t)j0 * 64) * HH;

#pragma unroll
    for (int it = 0; it < 16; it++) {
        int f  = tid + it * 128;
        int r  = f >> 5;
        int c4 = f & 31;
        cp16(sQa + (r * KST + c4 * 4) * 4, Qb + r * HH + c4 * 4);
        cp16(sKa + (r * KST + c4 * 4) * 4, Kb + r * HH + c4 * 4);
    }
    cp_commit();
#pragma unroll
    for (int it = 0; it < 16; it++) {
        int f  = tid + it * 128;
        int r  = f >> 5;
        int c4 = f & 31;
        cp16(sVa + (r * VST + c4 * 4) * 4, Vb + r * HH + c4 * 4);
    }
    cp_commit();

    asm volatile("cp.async.wait_group 1;");
    __syncthreads();

    uint32_t qa[16][4];
#pragma unroll
    for (int ks = 0; ks < 16; ks++) {
        const float* qrow = sQ + (16 * wid + g) * KST + ks * 8 + 2 * tg;
        float2 f0 = *(const float2*)qrow;
        float2 f1 = *(const float2*)(qrow + 8 * KST);
        qa[ks][0] = __float_as_uint(f0.x);
        qa[ks][1] = __float_as_uint(f1.x);
        qa[ks][2] = __float_as_uint(f0.y);
        qa[ks][3] = __float_as_uint(f1.y);
    }

    float o[16][4];
#pragma unroll
    for (int nn = 0; nn < 16; nn++)
#pragma unroll
        for (int v = 0; v < 4; v++) o[nn][v] = 0.0f;
    float m0 = -1e30f, m1 = -1e30f, l0 = 0.0f, l1 = 0.0f;

    const float SCL = 0.08838834764831845f * 1.4426950408889634f;
    const int src0 = (lane & ~3) | (tg >> 1);
    const int src1 = src0 + 2;
    const bool odd = (tg & 1);

    for (int j = j0; j < j1; j++) {
        if (j > j0) {
            asm volatile("cp.async.wait_group 1;");
            __syncthreads();
        }

        float c[8][4];
#pragma unroll
        for (int nn = 0; nn < 8; nn++)
#pragma unroll
            for (int v = 0; v < 4; v++) c[nn][v] = 0.0f;

#pragma unroll
        for (int ks = 0; ks < 16; ks++) {
#pragma unroll
            for (int nn = 0; nn < 8; nn++) {
                float2 kf = *(const float2*)&sK[(nn * 8 + g) * KST + ks * 8 + 2 * tg];
                mma8(c[nn], qa[ks], __float_as_uint(kf.x), __float_as_uint(kf.y));
            }
        }

        __syncthreads();
        if (j + 1 < j1) {
            const float* Kn = g_k + ((size_t)b * TT + (size_t)(j + 1) * 64) * HH;
#pragma unroll
            for (int it = 0; it < 16; it++) {
                int f  = tid + it * 128;
                int r  = f >> 5;
                int c4 = f & 31;
                cp16(sKa + (r * KST + c4 * 4) * 4, Kn + r * HH + c4 * 4);
            }
            cp_commit();
        }

#pragma unroll
        for (int nn = 0; nn < 8; nn++)
#pragma unroll
            for (int v = 0; v < 4; v++) c[nn][v] *= SCL;

        if (j == qt) {
            const int r0 = 16 * wid + g;
            const int r1 = r0 + 8;
#pragma unroll
            for (int nn = 0; nn < 8; nn++) {
                const int col = 8 * nn + 2 * tg;
                if (col     > r0) c[nn][0] = -1e30f;
                if (col + 1 > r0) c[nn][1] = -1e30f;
                if (col     > r1) c[nn][2] = -1e30f;
                if (col + 1 > r1) c[nn][3] = -1e30f;
            }
        }

        float rm0 = -1e30f, rm1 = -1e30f;
#pragma unroll
        for (int nn = 0; nn < 8; nn++) {
            rm0 = fmaxf(rm0, fmaxf(c[nn][0], c[nn][1]));
            rm1 = fmaxf(rm1, fmaxf(c[nn][2], c[nn][3]));
        }
        rm0 = fmaxf(rm0, __shfl_xor_sync(0xffffffffu, rm0, 1));
        rm0 = fmaxf(rm0, __shfl_xor_sync(0xffffffffu, rm0, 2));
        rm1 = fmaxf(rm1, __shfl_xor_sync(0xffffffffu, rm1, 1));
        rm1 = fmaxf(rm1, __shfl_xor_sync(0xffffffffu, rm1, 2));

        const float m0n = fmaxf(m0, rm0);
        const float m1n = fmaxf(m1, rm1);
        const float a0  = fex2(m0 - m0n);
        const float a1  = fex2(m1 - m1n);

        float rs0 = 0.0f, rs1 = 0.0f;
#pragma unroll
        for (int nn = 0; nn < 8; nn++) {
            c[nn][0] = fex2(c[nn][0] - m0n);
            c[nn][1] = fex2(c[nn][1] - m0n);
            c[nn][2] = fex2(c[nn][2] - m1n);
            c[nn][3] = fex2(c[nn][3] - m1n);
            rs0 += c[nn][0] + c[nn][1];
            rs1 += c[nn][2] + c[nn][3];
        }
        rs0 += __shfl_xor_sync(0xffffffffu, rs0, 1);
        rs0 += __shfl_xor_sync(0xffffffffu, rs0, 2);
        rs1 += __shfl_xor_sync(0xffffffffu, rs1, 1);
        rs1 += __shfl_xor_sync(0xffffffffu, rs1, 2);

        l0 = l0 * a0 + rs0;
        l1 = l1 * a1 + rs1;
        m0 = m0n;
        m1 = m1n;

#pragma unroll
        for (int nn = 0; nn < 16; nn++) {
            o[nn][0] *= a0; o[nn][1] *= a0;
            o[nn][2] *= a1; o[nn][3] *= a1;
        }

#pragma unroll
        for (int nn = 0; nn < 8; nn++)
#pragma unroll
            for (int v = 0; v < 4; v++) c[nn][v] = tf32r(c[nn][v]);

        if (j + 1 < j1) asm volatile("cp.async.wait_group 1;");
        else            asm volatile("cp.async.wait_group 0;");
        __syncthreads();

#pragma unroll
        for (int kk = 0; kk < 8; kk++) {
            float v00 = __shfl_sync(0xffffffffu, c[kk][0], src0);
            float v01 = __shfl_sync(0xffffffffu, c[kk][1], src0);
            float v10 = __shfl_sync(0xffffffffu, c[kk][2], src0);
            float v11 = __shfl_sync(0xffffffffu, c[kk][3], src0);
            float v20 = __shfl_sync(0xffffffffu, c[kk][0], src1);
            float v21 = __shfl_sync(0xffffffffu, c[kk][1], src1);
            float v30 = __shfl_sync(0xffffffffu, c[kk][2], src1);
            float v31 = __shfl_sync(0xffffffffu, c[kk][3], src1);
            uint32_t pa[4];
            pa[0] = __float_as_uint(odd ? v01 : v00);
            pa[1] = __float_as_uint(odd ? v11 : v10);
            pa[2] = __float_as_uint(odd ? v21 : v20);
            pa[3] = __float_as_uint(odd ? v31 : v30);
#pragma unroll
            for (int nn = 0; nn < 16; nn++) {
                const int base = (kk * 8 + tg) * VST + 8 * nn + g;
                uint32_t b0 = __float_as_uint(sV[base]);
                uint32_t b1 = __float_as_uint(sV[base + 4 * VST]);
                mma8(o[nn], pa, b0, b1);
            }
        }

        __syncthreads();
        if (j + 1 < j1) {
            const float* Vn = g_v + ((size_t)b * TT + (size_t)(j + 1) * 64) * HH;
#pragma unroll
            for (int it = 0; it < 16; it++) {
                int f  = tid + it * 128;
                int r  = f >> 5;
                int c4 = f & 31;
                cp16(sVa + (r * VST + c4 * 4) * 4, Vn + r * HH + c4 * 4);
            }
            cp_commit();
        }
    }

    // ----- epilogue -----
    const int r0 = 16 * wid + g;
    if (part == 3) {
        const float inv0 = 1.0f / l0;
        const float inv1 = 1.0f / l1;
        float* p0 = Out + ((size_t)b * TT + qt * 64 + r0) * HH;
        float* p1 = p0 + 8 * HH;
#pragma unroll
        for (int nn = 0; nn < 16; nn++) {
            const int col = 8 * nn + 2 * tg;
            *(float2*)(p0 + col) = make_float2(o[nn][0] * inv0, o[nn][1] * inv0);
            *(float2*)(p1 + col) = make_float2(o[nn][2] * inv1, o[nn][3] * inv1);
        }
    } else {
        const int pidx = (qt - 10) * 8 + b;
        float* p0 = g_po[part][pidx] + r0 * 128;
        float* p1 = p0 + 8 * 128;
#pragma unroll
        for (int nn = 0; nn < 16; nn++) {
            const int col = 8 * nn + 2 * tg;
            *(float2*)(p0 + col) = make_float2(o[nn][0], o[nn][1]);
            *(float2*)(p1 + col) = make_float2(o[nn][2], o[nn][3]);
        }
        if (tg == 0) {
            g_pm[part][pidx][r0]     = m0;
            g_pm[part][pidx][r0 + 8] = m1;
            g_pl[part][pidx][r0]     = l0;
            g_pl[part][pidx][r0 + 8] = l1;
        }
    }
}

// ---------------------------------------------------------------------------
// Combine split-KV partials (2 or 3 parts). Grid 704 (176 tiles x 4 quarters).
// ---------------------------------------------------------------------------
__global__ __launch_bounds__(256) void combine_kernel(float* __restrict__ Out)
{
    const int idx4 = blockIdx.x >> 2;       // 0..175
    const int quar = blockIdx.x & 3;
    const int qt   = 10 + (idx4 >> 3);
    const int b    = idx4 & 7;
    const int npt  = (qt >= 24) ? 3 : 2;
    const int tid  = threadIdx.x;

    const float* O0 = g_po[0][idx4];
    const float* O1 = g_po[1][idx4];
    const float* O2 = g_po[2][idx4];
    const float* M0 = g_pm[0][idx4];
    const float* M1 = g_pm[1][idx4];
    const float* M2 = g_pm[2][idx4];
    const float* L0 = g_pl[0][idx4];
    const float* L1 = g_pl[1][idx4];
    const float* L2 = g_pl[2][idx4];
    float* dst = Out + ((size_t)b * TT + (size_t)qt * 64) * HH;

#pragma unroll
    for (int it = 0; it < 2; it++) {
        int f  = tid + it * 256;
        int r  = quar * 16 + (f >> 5);
        int c4 = f & 31;
        float m0v = M0[r], m1v = M1[r];
        float mv  = fmaxf(m0v, m1v);
        float m2v = -1e30f;
        if (npt == 3) { m2v = M2[r]; mv = fmaxf(mv, m2v); }
        float w0  = fex2(m0v - mv);
        float w1  = fex2(m1v - mv);
        float den = L0[r] * w0 + L1[r] * w1;
        float4 a  = *(const float4*)(O0 + r * 128 + c4 * 4);
        float4 bb = *(const float4*)(O1 + r * 128 + c4 * 4);
        float rx = a.x * w0 + bb.x * w1;
        float ry = a.y * w0 + bb.y * w1;
        float rz = a.z * w0 + bb.z * w1;
        float rw = a.w * w0 + bb.w * w1;
        if (npt == 3) {
            float w2 = fex2(m2v - mv);
            den += L2[r] * w2;
            float4 cc = *(const float4*)(O2 + r * 128 + c4 * 4);
            rx += cc.x * w2; ry += cc.y * w2;
            rz += cc.z * w2; rw += cc.w * w2;
        }
        float inv = 1.0f / den;
        *(float4*)(dst + r * 128 + c4 * 4) =
            make_float4(rx * inv, ry * inv, rz * inv, rw * inv);
    }
}

// ---------------------------------------------------------------------------
extern "C" void kernel_launch(void* const* d_in, const int* in_sizes, int n_in,
                              void* d_out, int out_size)
{
    const float* x  = (const float*)d_in[0];
    const float* Wq = (const float*)d_in[1];
    const float* Wk = (const float*)d_in[2];
    const float* Wv = (const float*)d_in[3];
    float* out = (float*)d_out;

    (void)in_sizes; (void)n_in; (void)out_size;

    const int gemm_smem = 3 * STG_FL * (int)sizeof(float);
    cudaFuncSetAttribute(qkv_mma_kernel,
                         cudaFuncAttributeMaxDynamicSharedMemorySize, gemm_smem);
    qkv_mma_kernel<<<dim3(3, (BB * TT) / 128), 128, gemm_smem>>>(x, Wq, Wk, Wv);

    const int attn_smem = 64 * (2 * KST + VST) * (int)sizeof(float);
    cudaFuncSetAttribute(attn_mma_kernel,
                         cudaFuncAttributeMaxDynamicSharedMemorySize, attn_smem);
    attn_mma_kernel<<<496, 128, attn_smem>>>(out);

    combine_kernel<<<704, 256>>>(out);
}

// round 16
// speedup vs baseline: 1.2194x; 1.0359x over previous
#include <cuda_runtime.h>
#include <cstdint>
#include <cstddef>

#define BB 8
#define TT 2048
#define CC 1024
#define HH 128

// Scratch (device globals — no runtime alloc).
__device__ float g_q[BB * TT * HH];   // d-interleaved layout
__device__ float g_k[BB * TT * HH];   // d-interleaved layout
__device__ float g_v[BB * TT * HH];   // natural layout
__device__ int   g_done[BB];          // per-batch GEMM completion counters (zero-init)
// Split-KV partials: [part 0..2][(qt-10)*8+b][64*128] unnormalized O; m,l rows.
__device__ float g_po[3][176][64 * 128];
__device__ float g_pm[3][176][64];
__device__ float g_pl[3][176][64];

// Attention job table (62 slots), strict LPT order (descending KV-tiles).
// part: 0/1/2 = split piece; 3 = full tile (qt < 10).
// Split rule: np = (qt>=24)?3:2, n = qt+1, piece p covers [p*n/np, (p+1)*n/np).
__constant__ signed char c_qt[62] = {
    23,23,22, 22,21,21,20,30,31,31,
    20,19,19,18, 9,27,28,28,29,29,29,30,30,31,
    18,17,17,16, 8,24,25,25,26,26,26,27,27,28,
    16,15,15,14, 7,24,24,25,
    14,13,13,12, 6,
    12,11,11,10, 5,
    10, 4, 3, 2, 1, 0 };
__constant__ signed char c_part[62] = {
     0, 1, 1,  0, 0, 1, 1, 2, 1, 2,
     0, 0, 1, 1, 3, 2, 1, 2, 0, 1, 2, 0, 1, 0,
     0, 0, 1, 1, 3, 2, 1, 2, 0, 1, 2, 0, 1, 0,
     0, 0, 1, 1, 3, 0, 1, 0,
     0, 0, 1, 1, 3,
     0, 0, 1, 1, 3,
     0, 3, 3, 3, 3, 3 };

// ---------------------------------------------------------------------------
// Helpers
// ---------------------------------------------------------------------------
__device__ __forceinline__ float tf32r(float x) {
    uint32_t u;
    asm("cvt.rna.tf32.f32 %0, %1;" : "=r"(u) : "f"(x));
    return __uint_as_float(u);
}
__device__ __forceinline__ uint32_t tf32u(float x) {
    uint32_t u;
    asm("cvt.rna.tf32.f32 %0, %1;" : "=r"(u) : "f"(x));
    return u;
}
__device__ __forceinline__ void cp16(uint32_t saddr, const float* gaddr) {
    asm volatile("cp.async.cg.shared.global [%0], [%1], 16;"
                 :: "r"(saddr), "l"(gaddr));
}
__device__ __forceinline__ void cp_commit() {
    asm volatile("cp.async.commit_group;");
}
__device__ __forceinline__ float fex2(float x) {
    float r;
    asm("ex2.approx.f32 %0, %1;" : "=f"(r) : "f"(x));
    return r;
}
__device__ __forceinline__ void mma8(float* c, const uint32_t* a,
                                     uint32_t b0, uint32_t b1) {
    asm volatile(
        "mma.sync.aligned.m16n8k8.row.col.f32.tf32.tf32.f32 "
        "{%0,%1,%2,%3}, {%4,%5,%6,%7}, {%8,%9}, {%0,%1,%2,%3};"
        : "+f"(c[0]), "+f"(c[1]), "+f"(c[2]), "+f"(c[3])
        : "r"(a[0]), "r"(a[1]), "r"(a[2]), "r"(a[3]), "r"(b0), "r"(b1));
}

#define AST 36
#define BST 136
#define A_FL (128 * AST)
#define B_FL (32 * BST)
#define STG_FL (A_FL + B_FL)
#define KST 136
#define VST 136
#define N_GEMM 384

// ---------------------------------------------------------------------------
// Fused kernel: bids [0,384) = GEMM role; [384,880) = attention role.
// ---------------------------------------------------------------------------
__global__ __launch_bounds__(128, 2) void fused_kernel(
    const float* __restrict__ X,
    const float* __restrict__ Wq,
    const float* __restrict__ Wk,
    const float* __restrict__ Wv,
    float* __restrict__ Out)
{
    extern __shared__ float smem[];
    const int bid  = blockIdx.x;
    const int tid  = threadIdx.x;
    const int wid  = tid >> 5;
    const int lane = tid & 31;
    const int g    = lane >> 2;
    const int tg   = lane & 3;

    if (bid < N_GEMM) {
        // ================= GEMM role =================
        const int proj = bid % 3;
        const int mblk = bid / 3;          // ascending -> batches complete in order
        const float* __restrict__ W = (proj == 0) ? Wq : (proj == 1) ? Wk : Wv;
        float* __restrict__ out     = (proj == 0) ? g_q : (proj == 1) ? g_k : g_v;

        const int wm = wid & 1;
        const int wn = wid >> 1;
        const uint32_t smema = (uint32_t)__cvta_generic_to_shared(smem);
        const float* Xb = X + (size_t)mblk * 128 * CC;

        auto issue_chunk = [&](int kc) {
            const uint32_t sAa = smema + (uint32_t)((kc % 3) * STG_FL) * 4;
            const uint32_t sBa = sAa + A_FL * 4;
#pragma unroll
            for (int it = 0; it < 8; it++) {
                int f  = tid + it * 128;
                int r  = f >> 3;
                int c4 = f & 7;
                cp16(sAa + (r * AST + c4 * 4) * 4, Xb + (size_t)r * CC + kc * 32 + c4 * 4);
            }
#pragma unroll
            for (int it = 0; it < 8; it++) {
                int f  = tid + it * 128;
                int r  = f >> 5;
                int c4 = f & 31;
                cp16(sBa + (r * BST + c4 * 4) * 4, W + (size_t)(kc * 32 + r) * HH + c4 * 4);
            }
            cp_commit();
        };

        float acc[4][8][4];
#pragma unroll
        for (int i = 0; i < 4; i++)
#pragma unroll
            for (int n = 0; n < 8; n++)
#pragma unroll
                for (int v = 0; v < 4; v++) acc[i][n][v] = 0.0f;

        issue_chunk(0);
        issue_chunk(1);

        for (int kc = 0; kc < 32; kc++) {
            if (kc < 31) asm volatile("cp.async.wait_group 1;");
            else         asm volatile("cp.async.wait_group 0;");
            __syncthreads();
            if (kc + 2 < 32) issue_chunk(kc + 2);

            const float* aB = smem + (kc % 3) * STG_FL;
            const float* bB = aB + A_FL;

#pragma unroll
            for (int ks = 0; ks < 4; ks++) {
                uint32_t af[4][4];
#pragma unroll
                for (int i = 0; i < 4; i++) {
                    const int base = (wm * 64 + i * 16 + g) * AST + ks * 8 + tg;
                    af[i][0] = tf32u(aB[base]);
                    af[i][1] = tf32u(aB[base + 8 * AST]);
                    af[i][2] = tf32u(aB[base + 4]);
                    af[i][3] = tf32u(aB[base + 8 * AST + 4]);
                }
#pragma unroll
                for (int n = 0; n < 8; n++) {
                    const int base = (ks * 8 + tg) * BST + wn * 64 + n * 8 + g;
                    uint32_t b0 = tf32u(bB[base]);
                    uint32_t b1 = tf32u(bB[base + 4 * BST]);
#pragma unroll
                    for (int i = 0; i < 4; i++)
                        mma8(acc[i][n], af[i], b0, b1);
                }
            }
        }

        const int np = (tg < 2) ? (4 * tg) : (4 * tg - 7);
#pragma unroll
        for (int i = 0; i < 4; i++) {
            const int r0 = mblk * 128 + wm * 64 + i * 16 + g;
#pragma unroll
            for (int n = 0; n < 8; n++) {
                const int gbase = wn * 64 + n * 8;
                float v0 = tf32r(acc[i][n][0]);
                float v1 = tf32r(acc[i][n][1]);
                float v2 = tf32r(acc[i][n][2]);
                float v3 = tf32r(acc[i][n][3]);
                float* d0 = out + (size_t)r0 * HH;
                float* d1 = d0 + 8 * HH;
                if (proj < 2) {
                    d0[gbase + np]     = v0;
                    d0[gbase + np + 2] = v1;
                    d1[gbase + np]     = v2;
                    d1[gbase + np + 2] = v3;
                } else {
                    *(float2*)(d0 + gbase + 2 * tg) = make_float2(v0, v1);
                    *(float2*)(d1 + gbase + 2 * tg) = make_float2(v2, v3);
                }
            }
        }

        // signal batch completion
        __syncthreads();
        __threadfence();
        if (tid == 0) atomicAdd(&g_done[mblk >> 4], 1);
        return;
    }

    // ================= Attention role =================
    const int j = bid - N_GEMM;
    int slot, b;
    if (j < 372) { slot = j / 6;        b = j % 6; }          // batches 0-5, LPT
    else         { slot = (j - 372) / 2; b = 6 + ((j - 372) & 1); }
    const int qt   = c_qt[slot];
    const int part = c_part[slot];
    const int n    = qt + 1;
    const int npt  = (qt >= 24) ? 3 : 2;
    int j0, j1;
    if (part == 3) { j0 = 0; j1 = n; }
    else           { j0 = (part * n) / npt; j1 = ((part + 1) * n) / npt; }

    // wait for this batch's GEMM (48 CTAs)
    if (tid == 0) {
        volatile int* flag = &g_done[b];
        while (*flag < 48) { }
    }
    __syncthreads();
    __threadfence();

    float* sQ = smem;
    float* sK = sQ + 64 * KST;
    float* sV = sK + 64 * KST;

    const uint32_t sQa = (uint32_t)__cvta_generic_to_shared(sQ);
    const uint32_t sKa = (uint32_t)__cvta_generic_to_shared(sK);
    const uint32_t sVa = (uint32_t)__cvta_generic_to_shared(sV);

    const float* Qb = g_q + ((size_t)b * TT + (size_t)qt * 64) * HH;
    const float* Kb = g_k + ((size_t)b * TT + (size_t)j0 * 64) * HH;
    const float* Vb = g_v + ((size_t)b * TT + (size_t)j0 * 64) * HH;

#pragma unroll
    for (int it = 0; it < 16; it++) {
        int f  = tid + it * 128;
        int r  = f >> 5;
        int c4 = f & 31;
        cp16(sQa + (r * KST + c4 * 4) * 4, Qb + r * HH + c4 * 4);
        cp16(sKa + (r * KST + c4 * 4) * 4, Kb + r * HH + c4 * 4);
    }
    cp_commit();
#pragma unroll
    for (int it = 0; it < 16; it++) {
        int f  = tid + it * 128;
        int r  = f >> 5;
        int c4 = f & 31;
        cp16(sVa + (r * VST + c4 * 4) * 4, Vb + r * HH + c4 * 4);
    }
    cp_commit();

    asm volatile("cp.async.wait_group 1;");
    __syncthreads();

    uint32_t qa[16][4];
#pragma unroll
    for (int ks = 0; ks < 16; ks++) {
        const float* qrow = sQ + (16 * wid + g) * KST + ks * 8 + 2 * tg;
        float2 f0 = *(const float2*)qrow;
        float2 f1 = *(const float2*)(qrow + 8 * KST);
        qa[ks][0] = __float_as_uint(f0.x);
        qa[ks][1] = __float_as_uint(f1.x);
        qa[ks][2] = __float_as_uint(f0.y);
        qa[ks][3] = __float_as_uint(f1.y);
    }

    float o[16][4];
#pragma unroll
    for (int nn = 0; nn < 16; nn++)
#pragma unroll
        for (int v = 0; v < 4; v++) o[nn][v] = 0.0f;
    float m0 = -1e30f, m1 = -1e30f, l0 = 0.0f, l1 = 0.0f;

    const float SCL = 0.08838834764831845f * 1.4426950408889634f;
    const int src0 = (lane & ~3) | (tg >> 1);
    const int src1 = src0 + 2;
    const bool odd = (tg & 1);

    for (int jj = j0; jj < j1; jj++) {
        if (jj > j0) {
            asm volatile("cp.async.wait_group 1;");
            __syncthreads();
        }

        float c[8][4];
#pragma unroll
        for (int nn = 0; nn < 8; nn++)
#pragma unroll
            for (int v = 0; v < 4; v++) c[nn][v] = 0.0f;

#pragma unroll
        for (int ks = 0; ks < 16; ks++) {
#pragma unroll
            for (int nn = 0; nn < 8; nn++) {
                float2 kf = *(const float2*)&sK[(nn * 8 + g) * KST + ks * 8 + 2 * tg];
                mma8(c[nn], qa[ks], __float_as_uint(kf.x), __float_as_uint(kf.y));
            }
        }

        __syncthreads();
        if (jj + 1 < j1) {
            const float* Kn = g_k + ((size_t)b * TT + (size_t)(jj + 1) * 64) * HH;
#pragma unroll
            for (int it = 0; it < 16; it++) {
                int f  = tid + it * 128;
                int r  = f >> 5;
                int c4 = f & 31;
                cp16(sKa + (r * KST + c4 * 4) * 4, Kn + r * HH + c4 * 4);
            }
            cp_commit();
        }

#pragma unroll
        for (int nn = 0; nn < 8; nn++)
#pragma unroll
            for (int v = 0; v < 4; v++) c[nn][v] *= SCL;

        if (jj == qt) {
            const int r0 = 16 * wid + g;
            const int r1 = r0 + 8;
#pragma unroll
            for (int nn = 0; nn < 8; nn++) {
                const int col = 8 * nn + 2 * tg;
                if (col     > r0) c[nn][0] = -1e30f;
                if (col + 1 > r0) c[nn][1] = -1e30f;
                if (col     > r1) c[nn][2] = -1e30f;
                if (col + 1 > r1) c[nn][3] = -1e30f;
            }
        }

        float rm0 = -1e30f, rm1 = -1e30f;
#pragma unroll
        for (int nn = 0; nn < 8; nn++) {
            rm0 = fmaxf(rm0, fmaxf(c[nn][0], c[nn][1]));
            rm1 = fmaxf(rm1, fmaxf(c[nn][2], c[nn][3]));
        }
        rm0 = fmaxf(rm0, __shfl_xor_sync(0xffffffffu, rm0, 1));
        rm0 = fmaxf(rm0, __shfl_xor_sync(0xffffffffu, rm0, 2));
        rm1 = fmaxf(rm1, __shfl_xor_sync(0xffffffffu, rm1, 1));
        rm1 = fmaxf(rm1, __shfl_xor_sync(0xffffffffu, rm1, 2));

        const float m0n = fmaxf(m0, rm0);
        const float m1n = fmaxf(m1, rm1);
        const float a0  = fex2(m0 - m0n);
        const float a1  = fex2(m1 - m1n);

        float rs0 = 0.0f, rs1 = 0.0f;
#pragma unroll
        for (int nn = 0; nn < 8; nn++) {
            c[nn][0] = fex2(c[nn][0] - m0n);
            c[nn][1] = fex2(c[nn][1] - m0n);
            c[nn][2] = fex2(c[nn][2] - m1n);
            c[nn][3] = fex2(c[nn][3] - m1n);
            rs0 += c[nn][0] + c[nn][1];
            rs1 += c[nn][2] + c[nn][3];
        }
        rs0 += __shfl_xor_sync(0xffffffffu, rs0, 1);
        rs0 += __shfl_xor_sync(0xffffffffu, rs0, 2);
        rs1 += __shfl_xor_sync(0xffffffffu, rs1, 1);
        rs1 += __shfl_xor_sync(0xffffffffu, rs1, 2);

        l0 = l0 * a0 + rs0;
        l1 = l1 * a1 + rs1;
        m0 = m0n;
        m1 = m1n;

#pragma unroll
        for (int nn = 0; nn < 16; nn++) {
            o[nn][0] *= a0; o[nn][1] *= a0;
            o[nn][2] *= a1; o[nn][3] *= a1;
        }

#pragma unroll
        for (int nn = 0; nn < 8; nn++)
#pragma unroll
            for (int v = 0; v < 4; v++) c[nn][v] = tf32r(c[nn][v]);

        if (jj + 1 < j1) asm volatile("cp.async.wait_group 1;");
        else             asm volatile("cp.async.wait_group 0;");
        __syncthreads();

#pragma unroll
        for (int kk = 0; kk < 8; kk++) {
            float v00 = __shfl_sync(0xffffffffu, c[kk][0], src0);
            float v01 = __shfl_sync(0xffffffffu, c[kk][1], src0);
            float v10 = __shfl_sync(0xffffffffu, c[kk][2], src0);
            float v11 = __shfl_sync(0xffffffffu, c[kk][3], src0);
            float v20 = __shfl_sync(0xffffffffu, c[kk][0], src1);
            float v21 = __shfl_sync(0xffffffffu, c[kk][1], src1);
            float v30 = __shfl_sync(0xffffffffu, c[kk][2], src1);
            float v31 = __shfl_sync(0xffffffffu, c[kk][3], src1);
            uint32_t pa[4];
            pa[0] = __float_as_uint(odd ? v01 : v00);
            pa[1] = __float_as_uint(odd ? v11 : v10);
            pa[2] = __float_as_uint(odd ? v21 : v20);
            pa[3] = __float_as_uint(odd ? v31 : v30);
#pragma unroll
            for (int nn = 0; nn < 16; nn++) {
                const int base = (kk * 8 + tg) * VST + 8 * nn + g;
                uint32_t b0 = __float_as_uint(sV[base]);
                uint32_t b1 = __float_as_uint(sV[base + 4 * VST]);
                mma8(o[nn], pa, b0, b1);
            }
        }

        __syncthreads();
        if (jj + 1 < j1) {
            const float* Vn = g_v + ((size_t)b * TT + (size_t)(jj + 1) * 64) * HH;
#pragma unroll
            for (int it = 0; it < 16; it++) {
                int f  = tid + it * 128;
                int r  = f >> 5;
                int c4 = f & 31;
                cp16(sVa + (r * VST + c4 * 4) * 4, Vn + r * HH + c4 * 4);
            }
            cp_commit();
        }
    }

    // ----- epilogue -----
    const int r0 = 16 * wid + g;
    if (part == 3) {
        const float inv0 = 1.0f / l0;
        const float inv1 = 1.0f / l1;
        float* p0 = Out + ((size_t)b * TT + qt * 64 + r0) * HH;
        float* p1 = p0 + 8 * HH;
#pragma unroll
        for (int nn = 0; nn < 16; nn++) {
            const int col = 8 * nn + 2 * tg;
            *(float2*)(p0 + col) = make_float2(o[nn][0] * inv0, o[nn][1] * inv0);
            *(float2*)(p1 + col) = make_float2(o[nn][2] * inv1, o[nn][3] * inv1);
        }
    } else {
        const int pidx = (qt - 10) * 8 + b;
        float* p0 = g_po[part][pidx] + r0 * 128;
        float* p1 = p0 + 8 * 128;
#pragma unroll
        for (int nn = 0; nn < 16; nn++) {
            const int col = 8 * nn + 2 * tg;
            *(float2*)(p0 + col) = make_float2(o[nn][0], o[nn][1]);
            *(float2*)(p1 + col) = make_float2(o[nn][2], o[nn][3]);
        }
        if (tg == 0) {
            g_pm[part][pidx][r0]     = m0;
            g_pm[part][pidx][r0 + 8] = m1;
            g_pl[part][pidx][r0]     = l0;
            g_pl[part][pidx][r0 + 8] = l1;
        }
    }
}

// ---------------------------------------------------------------------------
// Combine split-KV partials (2 or 3 parts). Grid 704. Also resets g_done.
// ---------------------------------------------------------------------------
__global__ __launch_bounds__(256) void combine_kernel(float* __restrict__ Out)
{
    if (blockIdx.x == 0 && threadIdx.x < BB) g_done[threadIdx.x] = 0;

    const int idx4 = blockIdx.x >> 2;       // 0..175
    const int quar = blockIdx.x & 3;
    const int qt   = 10 + (idx4 >> 3);
    const int b    = idx4 & 7;
    const int npt  = (qt >= 24) ? 3 : 2;
    const int tid  = threadIdx.x;

    const float* O0 = g_po[0][idx4];
    const float* O1 = g_po[1][idx4];
    const float* O2 = g_po[2][idx4];
    const float* M0 = g_pm[0][idx4];
    const float* M1 = g_pm[1][idx4];
    const float* M2 = g_pm[2][idx4];
    const float* L0 = g_pl[0][idx4];
    const float* L1 = g_pl[1][idx4];
    const float* L2 = g_pl[2][idx4];
    float* dst = Out + ((size_t)b * TT + (size_t)qt * 64) * HH;

#pragma unroll
    for (int it = 0; it < 2; it++) {
        int f  = tid + it * 256;
        int r  = quar * 16 + (f >> 5);
        int c4 = f & 31;
        float m0v = M0[r], m1v = M1[r];
        float mv  = fmaxf(m0v, m1v);
        float m2v = -1e30f;
        if (npt == 3) { m2v = M2[r]; mv = fmaxf(mv, m2v); }
        float w0  = fex2(m0v - mv);
        float w1  = fex2(m1v - mv);
        float den = L0[r] * w0 + L1[r] * w1;
        float4 a  = *(const float4*)(O0 + r * 128 + c4 * 4);
        float4 bb = *(const float4*)(O1 + r * 128 + c4 * 4);
        float rx = a.x * w0 + bb.x * w1;
        float ry = a.y * w0 + bb.y * w1;
        float rz = a.z * w0 + bb.z * w1;
        float rw = a.w * w0 + bb.w * w1;
        if (npt == 3) {
            float w2 = fex2(m2v - mv);
            den += L2[r] * w2;
            float4 cc = *(const float4*)(O2 + r * 128 + c4 * 4);
            rx += cc.x * w2; ry += cc.y * w2;
            rz += cc.z * w2; rw += cc.w * w2;
        }
        float inv = 1.0f / den;
        *(float4*)(dst + r * 128 + c4 * 4) =
            make_float4(rx * inv, ry * inv, rz * inv, rw * inv);
    }
}

// ---------------------------------------------------------------------------
extern "C" void kernel_launch(void* const* d_in, const int* in_sizes, int n_in,
                              void* d_out, int out_size)
{
    const float* x  = (const float*)d_in[0];
    const float* Wq = (const float*)d_in[1];
    const float* Wk = (const float*)d_in[2];
    const float* Wv = (const float*)d_in[3];
    float* out = (float*)d_out;

    (void)in_sizes; (void)n_in; (void)out_size;

    const int fused_smem = 3 * STG_FL * (int)sizeof(float);   // >= attn needs
    cudaFuncSetAttribute(fused_kernel,
                         cudaFuncAttributeMaxDynamicSharedMemorySize, fused_smem);
    fused_kernel<<<N_GEMM + 496, 128, fused_smem>>>(x, Wq, Wk, Wv, out);

    combine_kernel<<<704, 256>>>(out);
}

// round 17
// speedup vs baseline: 1.3000x; 1.0660x over previous
#include <cuda_runtime.h>
#include <cstdint>
#include <cstddef>

#define BB 8
#define TT 2048
#define CC 1024
#define HH 128

// Scratch (device globals — no runtime alloc).
__device__ float g_q[BB * TT * HH];   // d-interleaved layout
__device__ float g_k[BB * TT * HH];   // d-interleaved layout
__device__ float g_v[BB * TT * HH];   // natural layout
__device__ int   g_done[BB];          // per-batch GEMM completion counters
// Split-KV partials: [part 0..4][(qt-6)*8+b][64*128] unnormalized O; m,l rows.
__device__ float g_po[5][208][64 * 128];
__device__ float g_pm[5][208][64];
__device__ float g_pl[5][208][64];

// Attention job table (96 slots/batch), strict LPT order (descending size).
// part 0..4 = split piece; 7 = full tile (qt < 6).
// np(qt) = 5 (qt>=28), 4 (qt>=20), 3 (qt>=10), 2 (qt>=6), 1 (qt<6).
// piece p covers [p*n/np, (p+1)*n/np), n = qt+1.
__constant__ signed char c_qt[96] = {
    // size 7 (16)
    31,31,30,27,27,27,27,26,26,26,25,25,24,19,19,18,
    // size 6 (42)
    31,31,31,30,30,30,30,29,29,29,29,29,28,28,28,28,26,25,25,24,24,
    24,23,23,23,23,22,22,22,21,21,20,19,18,18,17,17,17,16,16,15, 5,
    // size 5 (20)
    28,22,21,21,20,20,20,16,15,15,14,14,14,13,13,12, 9, 9, 8, 4,
    // size 4 (13)
    13,12,12,11,11,11,10,10, 8, 7, 7, 6, 3,
    // size 3 (3)
    10, 6, 2,
    // size 2, 1
     1, 0 };
__constant__ signed char c_part[96] = {
     2, 4, 4, 0, 1, 2, 3, 1, 2, 3, 1, 3, 3, 1, 2, 2,
     0, 1, 3, 0, 1, 2, 3, 0, 1, 2, 3, 4, 1, 2, 3, 4, 0, 0, 2, 0, 1,
     2, 0, 1, 2, 3, 1, 2, 3, 1, 3, 3, 0, 0, 1, 0, 1, 2, 1, 2, 2, 7,
     0, 0, 0, 2, 0, 1, 2, 0, 0, 1, 0, 1, 2, 1, 2, 2, 0, 1, 1, 7,
     0, 0, 1, 0, 1, 2, 1, 2, 0, 0, 1, 1, 7,
     0, 0, 7,
     7, 7 };

// ---------------------------------------------------------------------------
// Helpers
// ---------------------------------------------------------------------------
__device__ __forceinline__ float tf32r(float x) {
    uint32_t u;
    asm("cvt.rna.tf32.f32 %0, %1;" : "=r"(u) : "f"(x));
    return __uint_as_float(u);
}
__device__ __forceinline__ uint32_t tf32u(float x) {
    uint32_t u;
    asm("cvt.rna.tf32.f32 %0, %1;" : "=r"(u) : "f"(x));
    return u;
}
__device__ __forceinline__ void cp16(uint32_t saddr, const float* gaddr) {
    asm volatile("cp.async.cg.shared.global [%0], [%1], 16;"
                 :: "r"(saddr), "l"(gaddr));
}
__device__ __forceinline__ void cp_commit() {
    asm volatile("cp.async.commit_group;");
}
__device__ __forceinline__ float fex2(float x) {
    float r;
    asm("ex2.approx.f32 %0, %1;" : "=f"(r) : "f"(x));
    return r;
}
__device__ __forceinline__ void mma8(float* c, const uint32_t* a,
                                     uint32_t b0, uint32_t b1) {
    asm volatile(
        "mma.sync.aligned.m16n8k8.row.col.f32.tf32.tf32.f32 "
        "{%0,%1,%2,%3}, {%4,%5,%6,%7}, {%8,%9}, {%0,%1,%2,%3};"
        : "+f"(c[0]), "+f"(c[1]), "+f"(c[2]), "+f"(c[3])
        : "r"(a[0]), "r"(a[1]), "r"(a[2]), "r"(a[3]), "r"(b0), "r"(b1));
}

__device__ __forceinline__ int np_of(int qt) {
    return (qt >= 28) ? 5 : (qt >= 20) ? 4 : (qt >= 10) ? 3 : (qt >= 6) ? 2 : 1;
}

#define AST 36
#define BST 136
#define A_FL (128 * AST)
#define B_FL (32 * BST)
#define STG_FL (A_FL + B_FL)
#define KST 136
#define VST 136
#define N_GEMM 384
#define N_ATTN (96 * 8)

// ---------------------------------------------------------------------------
// Fused kernel: bids [0,384) = GEMM role; [384,384+768) = attention role.
// ---------------------------------------------------------------------------
__global__ __launch_bounds__(128, 2) void fused_kernel(
    const float* __restrict__ X,
    const float* __restrict__ Wq,
    const float* __restrict__ Wk,
    const float* __restrict__ Wv,
    float* __restrict__ Out)
{
    extern __shared__ float smem[];
    const int bid  = blockIdx.x;
    const int tid  = threadIdx.x;
    const int wid  = tid >> 5;
    const int lane = tid & 31;
    const int g    = lane >> 2;
    const int tg   = lane & 3;

    if (bid < N_GEMM) {
        // ================= GEMM role =================
        const int proj = bid % 3;
        const int mblk = bid / 3;          // ascending -> batches complete in order
        const float* __restrict__ W = (proj == 0) ? Wq : (proj == 1) ? Wk : Wv;
        float* __restrict__ out     = (proj == 0) ? g_q : (proj == 1) ? g_k : g_v;

        const int wm = wid & 1;
        const int wn = wid >> 1;
        const uint32_t smema = (uint32_t)__cvta_generic_to_shared(smem);
        const float* Xb = X + (size_t)mblk * 128 * CC;

        auto issue_chunk = [&](int kc) {
            const uint32_t sAa = smema + (uint32_t)((kc % 3) * STG_FL) * 4;
            const uint32_t sBa = sAa + A_FL * 4;
#pragma unroll
            for (int it = 0; it < 8; it++) {
                int f  = tid + it * 128;
                int r  = f >> 3;
                int c4 = f & 7;
                cp16(sAa + (r * AST + c4 * 4) * 4, Xb + (size_t)r * CC + kc * 32 + c4 * 4);
            }
#pragma unroll
            for (int it = 0; it < 8; it++) {
                int f  = tid + it * 128;
                int r  = f >> 5;
                int c4 = f & 31;
                cp16(sBa + (r * BST + c4 * 4) * 4, W + (size_t)(kc * 32 + r) * HH + c4 * 4);
            }
            cp_commit();
        };

        float acc[4][8][4];
#pragma unroll
        for (int i = 0; i < 4; i++)
#pragma unroll
            for (int n = 0; n < 8; n++)
#pragma unroll
                for (int v = 0; v < 4; v++) acc[i][n][v] = 0.0f;

        issue_chunk(0);
        issue_chunk(1);

        for (int kc = 0; kc < 32; kc++) {
            if (kc < 31) asm volatile("cp.async.wait_group 1;");
            else         asm volatile("cp.async.wait_group 0;");
            __syncthreads();
            if (kc + 2 < 32) issue_chunk(kc + 2);

            const float* aB = smem + (kc % 3) * STG_FL;
            const float* bB = aB + A_FL;

#pragma unroll
            for (int ks = 0; ks < 4; ks++) {
                uint32_t af[4][4];
#pragma unroll
                for (int i = 0; i < 4; i++) {
                    const int base = (wm * 64 + i * 16 + g) * AST + ks * 8 + tg;
                    af[i][0] = tf32u(aB[base]);
                    af[i][1] = tf32u(aB[base + 8 * AST]);
                    af[i][2] = tf32u(aB[base + 4]);
                    af[i][3] = tf32u(aB[base + 8 * AST + 4]);
                }
#pragma unroll
                for (int n = 0; n < 8; n++) {
                    const int base = (ks * 8 + tg) * BST + wn * 64 + n * 8 + g;
                    uint32_t b0 = tf32u(bB[base]);
                    uint32_t b1 = tf32u(bB[base + 4 * BST]);
#pragma unroll
                    for (int i = 0; i < 4; i++)
                        mma8(acc[i][n], af[i], b0, b1);
                }
            }
        }

        const int np = (tg < 2) ? (4 * tg) : (4 * tg - 7);
#pragma unroll
        for (int i = 0; i < 4; i++) {
            const int r0 = mblk * 128 + wm * 64 + i * 16 + g;
#pragma unroll
            for (int n = 0; n < 8; n++) {
                const int gbase = wn * 64 + n * 8;
                float v0 = tf32r(acc[i][n][0]);
                float v1 = tf32r(acc[i][n][1]);
                float v2 = tf32r(acc[i][n][2]);
                float v3 = tf32r(acc[i][n][3]);
                float* d0 = out + (size_t)r0 * HH;
                float* d1 = d0 + 8 * HH;
                if (proj < 2) {
                    d0[gbase + np]     = v0;
                    d0[gbase + np + 2] = v1;
                    d1[gbase + np]     = v2;
                    d1[gbase + np + 2] = v3;
                } else {
                    *(float2*)(d0 + gbase + 2 * tg) = make_float2(v0, v1);
                    *(float2*)(d1 + gbase + 2 * tg) = make_float2(v2, v3);
                }
            }
        }

        __syncthreads();
        __threadfence();
        if (tid == 0) atomicAdd(&g_done[mblk >> 4], 1);
        return;
    }

    // ================= Attention role =================
    const int j = bid - N_GEMM;
    int slot, b;
    if (j < 96 * 6) { slot = j / 6;            b = j % 6; }        // batches 0-5
    else            { slot = (j - 96 * 6) / 2; b = 6 + ((j - 96 * 6) & 1); }
    const int qt   = c_qt[slot];
    const int part = c_part[slot];
    const int n    = qt + 1;
    const int npt  = np_of(qt);
    int j0, j1;
    if (part == 7) { j0 = 0; j1 = n; }
    else           { j0 = (part * n) / npt; j1 = ((part + 1) * n) / npt; }

    if (tid == 0) {
        volatile int* flag = &g_done[b];
        while (*flag < 48) { }
    }
    __syncthreads();
    __threadfence();

    float* sQ = smem;
    float* sK = sQ + 64 * KST;
    float* sV = sK + 64 * KST;

    const uint32_t sQa = (uint32_t)__cvta_generic_to_shared(sQ);
    const uint32_t sKa = (uint32_t)__cvta_generic_to_shared(sK);
    const uint32_t sVa = (uint32_t)__cvta_generic_to_shared(sV);

    const float* Qb = g_q + ((size_t)b * TT + (size_t)qt * 64) * HH;
    const float* Kb = g_k + ((size_t)b * TT + (size_t)j0 * 64) * HH;
    const float* Vb = g_v + ((size_t)b * TT + (size_t)j0 * 64) * HH;

#pragma unroll
    for (int it = 0; it < 16; it++) {
        int f  = tid + it * 128;
        int r  = f >> 5;
        int c4 = f & 31;
        cp16(sQa + (r * KST + c4 * 4) * 4, Qb + r * HH + c4 * 4);
        cp16(sKa + (r * KST + c4 * 4) * 4, Kb + r * HH + c4 * 4);
    }
    cp_commit();
#pragma unroll
    for (int it = 0; it < 16; it++) {
        int f  = tid + it * 128;
        int r  = f >> 5;
        int c4 = f & 31;
        cp16(sVa + (r * VST + c4 * 4) * 4, Vb + r * HH + c4 * 4);
    }
    cp_commit();

    asm volatile("cp.async.wait_group 1;");
    __syncthreads();

    uint32_t qa[16][4];
#pragma unroll
    for (int ks = 0; ks < 16; ks++) {
        const float* qrow = sQ + (16 * wid + g) * KST + ks * 8 + 2 * tg;
        float2 f0 = *(const float2*)qrow;
        float2 f1 = *(const float2*)(qrow + 8 * KST);
        qa[ks][0] = __float_as_uint(f0.x);
        qa[ks][1] = __float_as_uint(f1.x);
        qa[ks][2] = __float_as_uint(f0.y);
        qa[ks][3] = __float_as_uint(f1.y);
    }

    float o[16][4];
#pragma unroll
    for (int nn = 0; nn < 16; nn++)
#pragma unroll
        for (int v = 0; v < 4; v++) o[nn][v] = 0.0f;
    float m0 = -1e30f, m1 = -1e30f, l0 = 0.0f, l1 = 0.0f;

    const float SCL = 0.08838834764831845f * 1.4426950408889634f;
    const int src0 = (lane & ~3) | (tg >> 1);
    const int src1 = src0 + 2;
    const bool odd = (tg & 1);

    for (int jj = j0; jj < j1; jj++) {
        if (jj > j0) {
            asm volatile("cp.async.wait_group 1;");
            __syncthreads();
        }

        float c[8][4];
#pragma unroll
        for (int nn = 0; nn < 8; nn++)
#pragma unroll
            for (int v = 0; v < 4; v++) c[nn][v] = 0.0f;

#pragma unroll
        for (int ks = 0; ks < 16; ks++) {
#pragma unroll
            for (int nn = 0; nn < 8; nn++) {
                float2 kf = *(const float2*)&sK[(nn * 8 + g) * KST + ks * 8 + 2 * tg];
                mma8(c[nn], qa[ks], __float_as_uint(kf.x), __float_as_uint(kf.y));
            }
        }

        __syncthreads();
        if (jj + 1 < j1) {
            const float* Kn = g_k + ((size_t)b * TT + (size_t)(jj + 1) * 64) * HH;
#pragma unroll
            for (int it = 0; it < 16; it++) {
                int f  = tid + it * 128;
                int r  = f >> 5;
                int c4 = f & 31;
                cp16(sKa + (r * KST + c4 * 4) * 4, Kn + r * HH + c4 * 4);
            }
            cp_commit();
        }

#pragma unroll
        for (int nn = 0; nn < 8; nn++)
#pragma unroll
            for (int v = 0; v < 4; v++) c[nn][v] *= SCL;

        if (jj == qt) {
            const int r0 = 16 * wid + g;
            const int r1 = r0 + 8;
#pragma unroll
            for (int nn = 0; nn < 8; nn++) {
                const int col = 8 * nn + 2 * tg;
                if (col     > r0) c[nn][0] = -1e30f;
                if (col + 1 > r0) c[nn][1] = -1e30f;
                if (col     > r1) c[nn][2] = -1e30f;
                if (col + 1 > r1) c[nn][3] = -1e30f;
            }
        }

        float rm0 = -1e30f, rm1 = -1e30f;
#pragma unroll
        for (int nn = 0; nn < 8; nn++) {
            rm0 = fmaxf(rm0, fmaxf(c[nn][0], c[nn][1]));
            rm1 = fmaxf(rm1, fmaxf(c[nn][2], c[nn][3]));
        }
        rm0 = fmaxf(rm0, __shfl_xor_sync(0xffffffffu, rm0, 1));
        rm0 = fmaxf(rm0, __shfl_xor_sync(0xffffffffu, rm0, 2));
        rm1 = fmaxf(rm1, __shfl_xor_sync(0xffffffffu, rm1, 1));
        rm1 = fmaxf(rm1, __shfl_xor_sync(0xffffffffu, rm1, 2));

        const float m0n = fmaxf(m0, rm0);
        const float m1n = fmaxf(m1, rm1);
        const float a0  = fex2(m0 - m0n);
        const float a1  = fex2(m1 - m1n);

        float rs0 = 0.0f, rs1 = 0.0f;
#pragma unroll
        for (int nn = 0; nn < 8; nn++) {
            c[nn][0] = fex2(c[nn][0] - m0n);
            c[nn][1] = fex2(c[nn][1] - m0n);
            c[nn][2] = fex2(c[nn][2] - m1n);
            c[nn][3] = fex2(c[nn][3] - m1n);
            rs0 += c[nn][0] + c[nn][1];
            rs1 += c[nn][2] + c[nn][3];
        }
        rs0 += __shfl_xor_sync(0xffffffffu, rs0, 1);
        rs0 += __shfl_xor_sync(0xffffffffu, rs0, 2);
        rs1 += __shfl_xor_sync(0xffffffffu, rs1, 1);
        rs1 += __shfl_xor_sync(0xffffffffu, rs1, 2);

        l0 = l0 * a0 + rs0;
        l1 = l1 * a1 + rs1;
        m0 = m0n;
        m1 = m1n;

#pragma unroll
        for (int nn = 0; nn < 16; nn++) {
            o[nn][0] *= a0; o[nn][1] *= a0;
            o[nn][2] *= a1; o[nn][3] *= a1;
        }

#pragma unroll
        for (int nn = 0; nn < 8; nn++)
#pragma unroll
            for (int v = 0; v < 4; v++) c[nn][v] = tf32r(c[nn][v]);

        if (jj + 1 < j1) asm volatile("cp.async.wait_group 1;");
        else             asm volatile("cp.async.wait_group 0;");
        __syncthreads();

#pragma unroll
        for (int kk = 0; kk < 8; kk++) {
            float v00 = __shfl_sync(0xffffffffu, c[kk][0], src0);
            float v01 = __shfl_sync(0xffffffffu, c[kk][1], src0);
            float v10 = __shfl_sync(0xffffffffu, c[kk][2], src0);
            float v11 = __shfl_sync(0xffffffffu, c[kk][3], src0);
            float v20 = __shfl_sync(0xffffffffu, c[kk][0], src1);
            float v21 = __shfl_sync(0xffffffffu, c[kk][1], src1);
            float v30 = __shfl_sync(0xffffffffu, c[kk][2], src1);
            float v31 = __shfl_sync(0xffffffffu, c[kk][3], src1);
            uint32_t pa[4];
            pa[0] = __float_as_uint(odd ? v01 : v00);
            pa[1] = __float_as_uint(odd ? v11 : v10);
            pa[2] = __float_as_uint(odd ? v21 : v20);
            pa[3] = __float_as_uint(odd ? v31 : v30);
#pragma unroll
            for (int nn = 0; nn < 16; nn++) {
                const int base = (kk * 8 + tg) * VST + 8 * nn + g;
                uint32_t b0 = __float_as_uint(sV[base]);
                uint32_t b1 = __float_as_uint(sV[base + 4 * VST]);
                mma8(o[nn], pa, b0, b1);
            }
        }

        __syncthreads();
        if (jj + 1 < j1) {
            const float* Vn = g_v + ((size_t)b * TT + (size_t)(jj + 1) * 64) * HH;
#pragma unroll
            for (int it = 0; it < 16; it++) {
                int f  = tid + it * 128;
                int r  = f >> 5;
                int c4 = f & 31;
                cp16(sVa + (r * VST + c4 * 4) * 4, Vn + r * HH + c4 * 4);
            }
            cp_commit();
        }
    }

    // ----- epilogue -----
    const int r0 = 16 * wid + g;
    if (part == 7) {
        const float inv0 = 1.0f / l0;
        const float inv1 = 1.0f / l1;
        float* p0 = Out + ((size_t)b * TT + qt * 64 + r0) * HH;
        float* p1 = p0 + 8 * HH;
#pragma unroll
        for (int nn = 0; nn < 16; nn++) {
            const int col = 8 * nn + 2 * tg;
            *(float2*)(p0 + col) = make_float2(o[nn][0] * inv0, o[nn][1] * inv0);
            *(float2*)(p1 + col) = make_float2(o[nn][2] * inv1, o[nn][3] * inv1);
        }
    } else {
        const int pidx = (qt - 6) * 8 + b;
        float* p0 = g_po[part][pidx] + r0 * 128;
        float* p1 = p0 + 8 * 128;
#pragma unroll
        for (int nn = 0; nn < 16; nn++) {
            const int col = 8 * nn + 2 * tg;
            *(float2*)(p0 + col) = make_float2(o[nn][0], o[nn][1]);
            *(float2*)(p1 + col) = make_float2(o[nn][2], o[nn][3]);
        }
        if (tg == 0) {
            g_pm[part][pidx][r0]     = m0;
            g_pm[part][pidx][r0 + 8] = m1;
            g_pl[part][pidx][r0]     = l0;
            g_pl[part][pidx][r0 + 8] = l1;
        }
    }
}

// ---------------------------------------------------------------------------
// Combine split-KV partials (2..5 parts). Grid 832 (208 tiles x 4 quarters).
// Also resets g_done for the next replay.
// ---------------------------------------------------------------------------
__global__ __launch_bounds__(256) void combine_kernel(float* __restrict__ Out)
{
    if (blockIdx.x == 0 && threadIdx.x < BB) g_done[threadIdx.x] = 0;

    const int idx4 = blockIdx.x >> 2;       // 0..207
    const int quar = blockIdx.x & 3;
    const int qt   = 6 + (idx4 >> 3);
    const int b    = idx4 & 7;
    const int npt  = np_of(qt);
    const int tid  = threadIdx.x;

    const float* Op[5];
    const float* Mp[5];
    const float* Lp[5];
#pragma unroll
    for (int p = 0; p < 5; p++) {
        Op[p] = g_po[p][idx4];
        Mp[p] = g_pm[p][idx4];
        Lp[p] = g_pl[p][idx4];
    }
    float* dst = Out + ((size_t)b * TT + (size_t)qt * 64) * HH;

#pragma unroll
    for (int it = 0; it < 2; it++) {
        int f  = tid + it * 256;
        int r  = quar * 16 + (f >> 5);
        int c4 = f & 31;
        float mv = -1e30f;
        for (int p = 0; p < npt; p++) mv = fmaxf(mv, Mp[p][r]);
        float den = 0.0f, rx = 0.0f, ry = 0.0f, rz = 0.0f, rw = 0.0f;
        for (int p = 0; p < npt; p++) {
            float w = fex2(Mp[p][r] - mv);
            den += Lp[p][r] * w;
            float4 a = *(const float4*)(Op[p] + r * 128 + c4 * 4);
            rx += a.x * w; ry += a.y * w; rz += a.z * w; rw += a.w * w;
        }
        float inv = 1.0f / den;
        *(float4*)(dst + r * 128 + c4 * 4) =
            make_float4(rx * inv, ry * inv, rz * inv, rw * inv);
    }
}

// ---------------------------------------------------------------------------
extern "C" void kernel_launch(void* const* d_in, const int* in_sizes, int n_in,
                              void* d_out, int out_size)
{
    const float* x  = (const float*)d_in[0];
    const float* Wq = (const float*)d_in[1];
    const float* Wk = (const float*)d_in[2];
    const float* Wv = (const float*)d_in[3];
    float* out = (float*)d_out;

    (void)in_sizes; (void)n_in; (void)out_size;

    const int fused_smem = 3 * STG_FL * (int)sizeof(float);
    cudaFuncSetAttribute(fused_kernel,
                         cudaFuncAttributeMaxDynamicSharedMemorySize, fused_smem);
    fused_kernel<<<N_GEMM + N_ATTN, 128, fused_smem>>>(x, Wq, Wk, Wv, out);

    combine_kernel<<<832, 256>>>(out);
}